// round 2
// baseline (speedup 1.0000x reference)
#include <cuda_runtime.h>
#include <cuda_bf16.h>
#include <cuda_pipeline.h>
#include <mma.h>

using namespace nvcuda;

#define N_SEQ   32768
#define D_MODEL 1024
#define KCTX    8
#define LCTX    9
#define HEADS   16
#define DHEAD   64
#define MROWS_C (N_SEQ * LCTX)   /* 294912 */

// ---------------- scratch (static device globals; no allocation) ----------------
__device__ float g_qn[(size_t)N_SEQ   * D_MODEL];  // LN(feat) with ln_q params
__device__ float g_cn[(size_t)MROWS_C * D_MODEL];  // LN(concat(feat,ctx)) with ln_c params
__device__ float g_q [(size_t)N_SEQ   * D_MODEL];
__device__ float g_k [(size_t)MROWS_C * D_MODEL];
__device__ float g_v [(size_t)MROWS_C * D_MODEL];
__device__ float g_o [(size_t)N_SEQ   * D_MODEL];  // attention output
__device__ float g_t [(size_t)N_SEQ   * D_MODEL];  // out-proj pre-epilogue

// ---------------- LayerNorm: one warp per row of 1024 ----------------
__global__ void __launch_bounds__(256) ln_kernel(
    const float* __restrict__ feat, const float* __restrict__ ctx,
    const float* __restrict__ qg, const float* __restrict__ qb,
    const float* __restrict__ cg, const float* __restrict__ cb)
{
    int warp = (blockIdx.x * blockDim.x + threadIdx.x) >> 5;
    int lane = threadIdx.x & 31;

    const float* src;
    const float* gp;
    const float* bp;
    float* dst;
    if (warp < N_SEQ) {
        src = feat + (size_t)warp * D_MODEL;
        gp = qg; bp = qb;
        dst = g_qn + (size_t)warp * D_MODEL;
    } else {
        int r = warp - N_SEQ;
        int n = r / LCTX, l = r % LCTX;
        src = (l == 0) ? (feat + (size_t)n * D_MODEL)
                       : (ctx + ((size_t)n * KCTX + (l - 1)) * D_MODEL);
        gp = cg; bp = cb;
        dst = g_cn + (size_t)r * D_MODEL;
    }

    float4 x[8];
    float s = 0.f, ss = 0.f;
#pragma unroll
    for (int j = 0; j < 8; j++) {
        x[j] = reinterpret_cast<const float4*>(src)[j * 32 + lane];
        s  += x[j].x + x[j].y + x[j].z + x[j].w;
        ss += x[j].x * x[j].x + x[j].y * x[j].y + x[j].z * x[j].z + x[j].w * x[j].w;
    }
#pragma unroll
    for (int o = 16; o; o >>= 1) {
        s  += __shfl_xor_sync(0xFFFFFFFFu, s,  o);
        ss += __shfl_xor_sync(0xFFFFFFFFu, ss, o);
    }
    float mean = s * (1.f / 1024.f);
    float var  = ss * (1.f / 1024.f) - mean * mean;
    float rstd = rsqrtf(var + 1e-5f);

#pragma unroll
    for (int j = 0; j < 8; j++) {
        float4 g4 = reinterpret_cast<const float4*>(gp)[j * 32 + lane];
        float4 b4 = reinterpret_cast<const float4*>(bp)[j * 32 + lane];
        float4 y;
        y.x = (x[j].x - mean) * rstd * g4.x + b4.x;
        y.y = (x[j].y - mean) * rstd * g4.y + b4.y;
        y.z = (x[j].z - mean) * rstd * g4.z + b4.z;
        y.w = (x[j].w - mean) * rstd * g4.w + b4.w;
        reinterpret_cast<float4*>(dst)[j * 32 + lane] = y;
    }
}

// ---------------- tf32 wmma GEMM: C[M,1024] = A[M,1024] @ B[1024,1024] ----------------
// BM=128, BN=128, BK=16. 8 warps (2x4), warp tile 64x32, m16n16k8 tf32 frags.
constexpr int BM = 128, BN = 128, BK = 16;

template<int MODE>  // 0: qn@Wq->q  1: cn@Wk->k  2: cn@Wv->v  3: o@Wout->t
__global__ void __launch_bounds__(256) gemm_kernel(const float* __restrict__ Bw)
{
    const float* A = (MODE == 0) ? g_qn : (MODE == 3) ? g_o : g_cn;
    float* C = (MODE == 0) ? g_q : (MODE == 1) ? g_k : (MODE == 2) ? g_v : g_t;

    __shared__ float As[2][BM][BK + 4];   // ldm 20
    __shared__ float Bs[2][BK][BN + 4];   // ldm 132

    int tid = threadIdx.x;
    size_t bm = (size_t)blockIdx.y * BM;
    int bn = blockIdx.x * BN;

    int wid = tid >> 5;
    int wm = (wid >> 2) * 64;
    int wn = (wid & 3) * 32;

    wmma::fragment<wmma::accumulator, 16, 16, 8, float> acc[4][2];
#pragma unroll
    for (int i = 0; i < 4; i++)
#pragma unroll
        for (int j = 0; j < 2; j++) wmma::fill_fragment(acc[i][j], 0.f);

    auto load_stage = [&](int buf, int kt) {
        // A tile 128x16 floats = 512 x 16B chunks, 2 per thread
#pragma unroll
        for (int i = 0; i < 2; i++) {
            int c = tid + i * 256;
            int r = c >> 2, col = (c & 3) * 4;
            __pipeline_memcpy_async(&As[buf][r][col],
                                    A + (bm + r) * D_MODEL + kt * BK + col, 16);
        }
        // B tile 16x128 floats = 512 x 16B chunks
#pragma unroll
        for (int i = 0; i < 2; i++) {
            int c = tid + i * 256;
            int r = c >> 5, col = (c & 31) * 4;
            __pipeline_memcpy_async(&Bs[buf][r][col],
                                    Bw + (size_t)(kt * BK + r) * D_MODEL + bn + col, 16);
        }
    };

    load_stage(0, 0);
    __pipeline_commit();

    constexpr int NT = D_MODEL / BK;  // 64
    for (int kt = 0; kt < NT; kt++) {
        if (kt + 1 < NT) load_stage((kt + 1) & 1, kt + 1);
        __pipeline_commit();
        __pipeline_wait_prior(1);
        __syncthreads();
        int buf = kt & 1;
#pragma unroll
        for (int kk = 0; kk < BK; kk += 8) {
            wmma::fragment<wmma::matrix_a, 16, 16, 8, wmma::precision::tf32, wmma::row_major> af[4];
            wmma::fragment<wmma::matrix_b, 16, 16, 8, wmma::precision::tf32, wmma::row_major> bf[2];
#pragma unroll
            for (int i = 0; i < 4; i++) {
                wmma::load_matrix_sync(af[i], &As[buf][wm + i * 16][kk], BK + 4);
#pragma unroll
                for (int t = 0; t < af[i].num_elements; t++)
                    af[i].x[t] = wmma::__float_to_tf32(af[i].x[t]);
            }
#pragma unroll
            for (int j = 0; j < 2; j++) {
                wmma::load_matrix_sync(bf[j], &Bs[buf][kk][wn + j * 16], BN + 4);
#pragma unroll
                for (int t = 0; t < bf[j].num_elements; t++)
                    bf[j].x[t] = wmma::__float_to_tf32(bf[j].x[t]);
            }
#pragma unroll
            for (int i = 0; i < 4; i++)
#pragma unroll
                for (int j = 0; j < 2; j++)
                    wmma::mma_sync(acc[i][j], af[i], bf[j], acc[i][j]);
        }
        __syncthreads();
    }

#pragma unroll
    for (int i = 0; i < 4; i++)
#pragma unroll
        for (int j = 0; j < 2; j++)
            wmma::store_matrix_sync(C + (bm + wm + i * 16) * D_MODEL + bn + wn + j * 16,
                                    acc[i][j], D_MODEL, wmma::mem_row_major);
}

// ---------------- attention: one warp per (n, h), L = 9 ----------------
__global__ void __launch_bounds__(256) attn_kernel()
{
    int warp = (blockIdx.x * blockDim.x + threadIdx.x) >> 5;
    int lane = threadIdx.x & 31;
    int n = warp >> 4;
    int h = warp & 15;

    size_t qoff = (size_t)n * D_MODEL + h * DHEAD + lane * 2;
    float2 q = *reinterpret_cast<const float2*>(g_q + qoff);

    float sc[LCTX];
#pragma unroll
    for (int l = 0; l < LCTX; l++) {
        size_t koff = (size_t)(n * LCTX + l) * D_MODEL + h * DHEAD + lane * 2;
        float2 kk = *reinterpret_cast<const float2*>(g_k + koff);
        float p = q.x * kk.x + q.y * kk.y;
#pragma unroll
        for (int o = 16; o; o >>= 1) p += __shfl_xor_sync(0xFFFFFFFFu, p, o);
        sc[l] = p * 0.125f;   // DIM_HEAD^-0.5
    }
    float m = sc[0];
#pragma unroll
    for (int l = 1; l < LCTX; l++) m = fmaxf(m, sc[l]);
    float sum = 0.f;
#pragma unroll
    for (int l = 0; l < LCTX; l++) { sc[l] = __expf(sc[l] - m); sum += sc[l]; }
    float inv = 1.f / sum;

    float ox = 0.f, oy = 0.f;
#pragma unroll
    for (int l = 0; l < LCTX; l++) {
        size_t voff = (size_t)(n * LCTX + l) * D_MODEL + h * DHEAD + lane * 2;
        float2 vv = *reinterpret_cast<const float2*>(g_v + voff);
        float p = sc[l] * inv;
        ox = fmaf(p, vv.x, ox);
        oy = fmaf(p, vv.y, oy);
    }
    *reinterpret_cast<float2*>(g_o + qoff) = make_float2(ox, oy);
}

// ---------------- epilogue: out = g_t + bout + feat ----------------
__global__ void __launch_bounds__(256) epilogue_kernel(
    const float* __restrict__ feat, const float* __restrict__ bout,
    float* __restrict__ out)
{
    size_t total4 = (size_t)N_SEQ * D_MODEL / 4;
    for (size_t i = (size_t)blockIdx.x * blockDim.x + threadIdx.x; i < total4;
         i += (size_t)gridDim.x * blockDim.x) {
        float4 t = reinterpret_cast<const float4*>(g_t)[i];
        float4 f = reinterpret_cast<const float4*>(feat)[i];
        int col = (int)((i * 4) & (D_MODEL - 1));
        float4 b = *reinterpret_cast<const float4*>(bout + col);
        float4 r;
        r.x = t.x + f.x + b.x;
        r.y = t.y + f.y + b.y;
        r.z = t.z + f.z + b.z;
        r.w = t.w + f.w + b.w;
        reinterpret_cast<float4*>(out)[i] = r;
    }
}

// ---------------- launch ----------------
extern "C" void kernel_launch(void* const* d_in, const int* in_sizes, int n_in,
                              void* d_out, int out_size)
{
    const float* feat = (const float*)d_in[0];
    const float* ctx  = (const float*)d_in[1];
    const float* qg   = (const float*)d_in[2];
    const float* qb   = (const float*)d_in[3];
    const float* cg   = (const float*)d_in[4];
    const float* cb   = (const float*)d_in[5];
    const float* Wq   = (const float*)d_in[6];
    const float* Wk   = (const float*)d_in[7];
    const float* Wv   = (const float*)d_in[8];
    const float* Wout = (const float*)d_in[9];
    const float* bout = (const float*)d_in[10];
    float* out = (float*)d_out;

    // 327680 rows total, 8 warps per block
    ln_kernel<<<(N_SEQ + MROWS_C) / 8, 256>>>(feat, ctx, qg, qb, cg, cb);

    gemm_kernel<0><<<dim3(D_MODEL / BN, N_SEQ   / BM), 256>>>(Wq);
    gemm_kernel<1><<<dim3(D_MODEL / BN, MROWS_C / BM), 256>>>(Wk);
    gemm_kernel<2><<<dim3(D_MODEL / BN, MROWS_C / BM), 256>>>(Wv);

    attn_kernel<<<(N_SEQ * HEADS) / 8, 256>>>();

    gemm_kernel<3><<<dim3(D_MODEL / BN, N_SEQ / BM), 256>>>(Wout);

    epilogue_kernel<<<8192, 256>>>(feat, bout, out);
}

// round 3
// speedup vs baseline: 2.8698x; 2.8698x over previous
#include <cuda_runtime.h>
#include <cuda_bf16.h>
#include <cuda_pipeline.h>
#include <mma.h>

using namespace nvcuda;

#define N_SEQ   32768
#define D_MODEL 1024
#define KCTX    8
#define LCTX    9
#define HEADS   16
#define DHEAD   64
#define MROWS_C (N_SEQ * LCTX)   /* 294912 */

// ---------------- scratch (static device globals; no allocation) ----------------
__device__ __nv_bfloat16 g_qn_h[(size_t)N_SEQ   * D_MODEL];
__device__ __nv_bfloat16 g_cn_h[(size_t)MROWS_C * D_MODEL];
__device__ __nv_bfloat16 g_o_h [(size_t)N_SEQ   * D_MODEL];   // attention output (bf16)
__device__ float g_q [(size_t)N_SEQ   * D_MODEL];
__device__ float g_k [(size_t)MROWS_C * D_MODEL];
__device__ float g_v [(size_t)MROWS_C * D_MODEL];
__device__ float g_t [(size_t)N_SEQ   * D_MODEL];
__device__ __nv_bfloat16 g_wq[(size_t)D_MODEL * D_MODEL];
__device__ __nv_bfloat16 g_wk[(size_t)D_MODEL * D_MODEL];
__device__ __nv_bfloat16 g_wv[(size_t)D_MODEL * D_MODEL];
__device__ __nv_bfloat16 g_wo[(size_t)D_MODEL * D_MODEL];

// ---------------- fp32 -> bf16 weight conversion (W selected by template) -------
template<int W>
__global__ void __launch_bounds__(256) cvt_kernel(const float* __restrict__ src)
{
    __nv_bfloat16* dst = (W == 0) ? g_wq : (W == 1) ? g_wk : (W == 2) ? g_wv : g_wo;
    int i = blockIdx.x * blockDim.x + threadIdx.x;   // one float4 per thread
    float4 v = reinterpret_cast<const float4*>(src)[i];
    __nv_bfloat162 a = __floats2bfloat162_rn(v.x, v.y);
    __nv_bfloat162 b = __floats2bfloat162_rn(v.z, v.w);
    uint2 u;
    u.x = *reinterpret_cast<unsigned int*>(&a);
    u.y = *reinterpret_cast<unsigned int*>(&b);
    reinterpret_cast<uint2*>(dst)[i] = u;
}

// ---------------- LayerNorm: one warp per row of 1024, bf16 output ----------------
__global__ void __launch_bounds__(256) ln_kernel(
    const float* __restrict__ feat, const float* __restrict__ ctx,
    const float* __restrict__ qg, const float* __restrict__ qb,
    const float* __restrict__ cg, const float* __restrict__ cb)
{
    int warp = (blockIdx.x * blockDim.x + threadIdx.x) >> 5;
    int lane = threadIdx.x & 31;

    const float* src;
    const float* gp;
    const float* bp;
    __nv_bfloat16* dst;
    if (warp < N_SEQ) {
        src = feat + (size_t)warp * D_MODEL;
        gp = qg; bp = qb;
        dst = g_qn_h + (size_t)warp * D_MODEL;
    } else {
        int r = warp - N_SEQ;
        int n = r / LCTX, l = r % LCTX;
        src = (l == 0) ? (feat + (size_t)n * D_MODEL)
                       : (ctx + ((size_t)n * KCTX + (l - 1)) * D_MODEL);
        gp = cg; bp = cb;
        dst = g_cn_h + (size_t)r * D_MODEL;
    }

    float4 x[8];
    float s = 0.f, ss = 0.f;
#pragma unroll
    for (int j = 0; j < 8; j++) {
        x[j] = reinterpret_cast<const float4*>(src)[j * 32 + lane];
        s  += x[j].x + x[j].y + x[j].z + x[j].w;
        ss += x[j].x * x[j].x + x[j].y * x[j].y + x[j].z * x[j].z + x[j].w * x[j].w;
    }
#pragma unroll
    for (int o = 16; o; o >>= 1) {
        s  += __shfl_xor_sync(0xFFFFFFFFu, s,  o);
        ss += __shfl_xor_sync(0xFFFFFFFFu, ss, o);
    }
    float mean = s * (1.f / 1024.f);
    float var  = ss * (1.f / 1024.f) - mean * mean;
    float rstd = rsqrtf(var + 1e-5f);

#pragma unroll
    for (int j = 0; j < 8; j++) {
        float4 g4 = reinterpret_cast<const float4*>(gp)[j * 32 + lane];
        float4 b4 = reinterpret_cast<const float4*>(bp)[j * 32 + lane];
        float yx = (x[j].x - mean) * rstd * g4.x + b4.x;
        float yy = (x[j].y - mean) * rstd * g4.y + b4.y;
        float yz = (x[j].z - mean) * rstd * g4.z + b4.z;
        float yw = (x[j].w - mean) * rstd * g4.w + b4.w;
        __nv_bfloat162 p0 = __floats2bfloat162_rn(yx, yy);
        __nv_bfloat162 p1 = __floats2bfloat162_rn(yz, yw);
        uint2 u;
        u.x = *reinterpret_cast<unsigned int*>(&p0);
        u.y = *reinterpret_cast<unsigned int*>(&p1);
        reinterpret_cast<uint2*>(dst)[j * 32 + lane] = u;
    }
}

// ---------------- bf16 wmma GEMM: C[M,1024] = A[M,1024] @ B[1024,1024], fp32 acc ----
constexpr int BM = 128, BN = 128, BK = 32;

template<int MODE>  // 0: qn@Wq->q  1: cn@Wk->k  2: cn@Wv->v  3: o@Wout->t
__global__ void __launch_bounds__(256) gemm_kernel()
{
    const __nv_bfloat16* A = (MODE == 0) ? g_qn_h : (MODE == 3) ? g_o_h : g_cn_h;
    const __nv_bfloat16* Bw = (MODE == 0) ? g_wq : (MODE == 1) ? g_wk
                            : (MODE == 2) ? g_wv : g_wo;
    float* C = (MODE == 0) ? g_q : (MODE == 1) ? g_k : (MODE == 2) ? g_v : g_t;

    __shared__ __nv_bfloat16 As[2][BM][BK + 8];   // ldm 40
    __shared__ __nv_bfloat16 Bs[2][BK][BN + 8];   // ldm 136

    int tid = threadIdx.x;
    size_t bm = (size_t)blockIdx.y * BM;
    int bn = blockIdx.x * BN;

    int wid = tid >> 5;
    int wm = (wid >> 2) * 64;
    int wn = (wid & 3) * 32;

    wmma::fragment<wmma::accumulator, 16, 16, 16, float> acc[4][2];
#pragma unroll
    for (int i = 0; i < 4; i++)
#pragma unroll
        for (int j = 0; j < 2; j++) wmma::fill_fragment(acc[i][j], 0.f);

    auto load_stage = [&](int buf, int kt) {
#pragma unroll
        for (int i = 0; i < 2; i++) {
            int c = tid + i * 256;
            int r = c >> 2, col = (c & 3) * 8;
            __pipeline_memcpy_async(&As[buf][r][col],
                                    A + (bm + r) * D_MODEL + kt * BK + col, 16);
        }
#pragma unroll
        for (int i = 0; i < 2; i++) {
            int c = tid + i * 256;
            int r = c >> 4, col = (c & 15) * 8;
            __pipeline_memcpy_async(&Bs[buf][r][col],
                                    Bw + (size_t)(kt * BK + r) * D_MODEL + bn + col, 16);
        }
    };

    load_stage(0, 0);
    __pipeline_commit();

    constexpr int NT = D_MODEL / BK;  // 32
    for (int kt = 0; kt < NT; kt++) {
        if (kt + 1 < NT) load_stage((kt + 1) & 1, kt + 1);
        __pipeline_commit();
        __pipeline_wait_prior(1);
        __syncthreads();
        int buf = kt & 1;
#pragma unroll
        for (int kk = 0; kk < BK; kk += 16) {
            wmma::fragment<wmma::matrix_a, 16, 16, 16, __nv_bfloat16, wmma::row_major> af[4];
            wmma::fragment<wmma::matrix_b, 16, 16, 16, __nv_bfloat16, wmma::row_major> bf[2];
#pragma unroll
            for (int i = 0; i < 4; i++)
                wmma::load_matrix_sync(af[i], &As[buf][wm + i * 16][kk], BK + 8);
#pragma unroll
            for (int j = 0; j < 2; j++)
                wmma::load_matrix_sync(bf[j], &Bs[buf][kk][wn + j * 16], BN + 8);
#pragma unroll
            for (int i = 0; i < 4; i++)
#pragma unroll
                for (int j = 0; j < 2; j++)
                    wmma::mma_sync(acc[i][j], af[i], bf[j], acc[i][j]);
        }
        __syncthreads();
    }

#pragma unroll
    for (int i = 0; i < 4; i++)
#pragma unroll
        for (int j = 0; j < 2; j++)
            wmma::store_matrix_sync(C + (bm + wm + i * 16) * D_MODEL + bn + wn + j * 16,
                                    acc[i][j], D_MODEL, wmma::mem_row_major);
}

// ---------------- attention: one warp per (n, h), L = 9, bf16 output ----------------
__global__ void __launch_bounds__(256) attn_kernel()
{
    int warp = (blockIdx.x * blockDim.x + threadIdx.x) >> 5;
    int lane = threadIdx.x & 31;
    int n = warp >> 4;
    int h = warp & 15;

    size_t qoff = (size_t)n * D_MODEL + h * DHEAD + lane * 2;
    float2 q = *reinterpret_cast<const float2*>(g_q + qoff);

    float sc[LCTX];
#pragma unroll
    for (int l = 0; l < LCTX; l++) {
        size_t koff = (size_t)(n * LCTX + l) * D_MODEL + h * DHEAD + lane * 2;
        float2 kk = *reinterpret_cast<const float2*>(g_k + koff);
        float p = q.x * kk.x + q.y * kk.y;
#pragma unroll
        for (int o = 16; o; o >>= 1) p += __shfl_xor_sync(0xFFFFFFFFu, p, o);
        sc[l] = p * 0.125f;
    }
    float m = sc[0];
#pragma unroll
    for (int l = 1; l < LCTX; l++) m = fmaxf(m, sc[l]);
    float sum = 0.f;
#pragma unroll
    for (int l = 0; l < LCTX; l++) { sc[l] = __expf(sc[l] - m); sum += sc[l]; }
    float inv = 1.f / sum;

    float ox = 0.f, oy = 0.f;
#pragma unroll
    for (int l = 0; l < LCTX; l++) {
        size_t voff = (size_t)(n * LCTX + l) * D_MODEL + h * DHEAD + lane * 2;
        float2 vv = *reinterpret_cast<const float2*>(g_v + voff);
        float p = sc[l] * inv;
        ox = fmaf(p, vv.x, ox);
        oy = fmaf(p, vv.y, oy);
    }
    __nv_bfloat162 o2 = __floats2bfloat162_rn(ox, oy);
    *reinterpret_cast<__nv_bfloat162*>(g_o_h + qoff) = o2;
}

// ---------------- epilogue: out = g_t + bout + feat ----------------
__global__ void __launch_bounds__(256) epilogue_kernel(
    const float* __restrict__ feat, const float* __restrict__ bout,
    float* __restrict__ out)
{
    size_t total4 = (size_t)N_SEQ * D_MODEL / 4;
    for (size_t i = (size_t)blockIdx.x * blockDim.x + threadIdx.x; i < total4;
         i += (size_t)gridDim.x * blockDim.x) {
        float4 t = reinterpret_cast<const float4*>(g_t)[i];
        float4 f = reinterpret_cast<const float4*>(feat)[i];
        int col = (int)((i * 4) & (D_MODEL - 1));
        float4 b = *reinterpret_cast<const float4*>(bout + col);
        float4 r;
        r.x = t.x + f.x + b.x;
        r.y = t.y + f.y + b.y;
        r.z = t.z + f.z + b.z;
        r.w = t.w + f.w + b.w;
        reinterpret_cast<float4*>(out)[i] = r;
    }
}

// ---------------- launch ----------------
extern "C" void kernel_launch(void* const* d_in, const int* in_sizes, int n_in,
                              void* d_out, int out_size)
{
    const float* feat = (const float*)d_in[0];
    const float* ctx  = (const float*)d_in[1];
    const float* qg   = (const float*)d_in[2];
    const float* qb   = (const float*)d_in[3];
    const float* cg   = (const float*)d_in[4];
    const float* cb   = (const float*)d_in[5];
    const float* Wq   = (const float*)d_in[6];
    const float* Wk   = (const float*)d_in[7];
    const float* Wv   = (const float*)d_in[8];
    const float* Wout = (const float*)d_in[9];
    const float* bout = (const float*)d_in[10];
    float* out = (float*)d_out;

    cvt_kernel<0><<<1024, 256>>>(Wq);
    cvt_kernel<1><<<1024, 256>>>(Wk);
    cvt_kernel<2><<<1024, 256>>>(Wv);
    cvt_kernel<3><<<1024, 256>>>(Wout);

    ln_kernel<<<(N_SEQ + MROWS_C) / 8, 256>>>(feat, ctx, qg, qb, cg, cb);

    gemm_kernel<0><<<dim3(D_MODEL / BN, N_SEQ   / BM), 256>>>();
    gemm_kernel<1><<<dim3(D_MODEL / BN, MROWS_C / BM), 256>>>();
    gemm_kernel<2><<<dim3(D_MODEL / BN, MROWS_C / BM), 256>>>();

    attn_kernel<<<(N_SEQ * HEADS) / 8, 256>>>();

    gemm_kernel<3><<<dim3(D_MODEL / BN, N_SEQ / BM), 256>>>();

    epilogue_kernel<<<8192, 256>>>(feat, bout, out);
}

// round 5
// speedup vs baseline: 3.5278x; 1.2293x over previous
#include <cuda_runtime.h>
#include <cuda_bf16.h>
#include <cuda_pipeline.h>
#include <mma.h>
#include <cstdint>

using namespace nvcuda;

#define N_SEQ   32768
#define D_MODEL 1024
#define KCTX    8
#define LCTX    9
#define HEADS   16
#define DHEAD   64
#define MROWS_C (N_SEQ * LCTX)   /* 294912 */

// ---------------- scratch (static device globals; no allocation) ----------------
__device__ __nv_bfloat16 g_qn_h[(size_t)N_SEQ   * D_MODEL];
__device__ __nv_bfloat16 g_cn_h[(size_t)MROWS_C * D_MODEL];
__device__ __nv_bfloat16 g_o_h [(size_t)N_SEQ   * D_MODEL];
__device__ float g_q [(size_t)N_SEQ   * D_MODEL];
__device__ float g_k [(size_t)MROWS_C * D_MODEL];
__device__ float g_v [(size_t)MROWS_C * D_MODEL];
__device__ float g_t [(size_t)N_SEQ   * D_MODEL];
// transposed bf16 weights: Wt[n][k] = W[k][n]  (K-major, same layout as A)
__device__ __nv_bfloat16 g_wqt[(size_t)D_MODEL * D_MODEL];
__device__ __nv_bfloat16 g_wkt[(size_t)D_MODEL * D_MODEL];
__device__ __nv_bfloat16 g_wvt[(size_t)D_MODEL * D_MODEL];
__device__ __nv_bfloat16 g_wot[(size_t)D_MODEL * D_MODEL];

// ---------------- weight convert + transpose: Wt[n][k] = bf16(W[k][n]) ---------
template<int W>
__global__ void __launch_bounds__(256) cvtT_kernel(const float* __restrict__ src)
{
    __nv_bfloat16* dst = (W == 0) ? g_wqt : (W == 1) ? g_wkt : (W == 2) ? g_wvt : g_wot;
    __shared__ float t[32][33];
    int tx = threadIdx.x & 31, ty = threadIdx.x >> 5;  // 32 x 8
    int n0 = blockIdx.x * 32, k0 = blockIdx.y * 32;
#pragma unroll
    for (int j = 0; j < 4; j++)
        t[ty + j * 8][tx] = src[(size_t)(k0 + ty + j * 8) * D_MODEL + n0 + tx];
    __syncthreads();
#pragma unroll
    for (int j = 0; j < 4; j++) {
        int n = ty + j * 8;
        dst[(size_t)(n0 + n) * D_MODEL + k0 + tx] = __float2bfloat16(t[tx][n]);
    }
}

// ---------------- LayerNorm: one warp per row of 1024, bf16 output ----------------
__global__ void __launch_bounds__(256) ln_kernel(
    const float* __restrict__ feat, const float* __restrict__ ctx,
    const float* __restrict__ qg, const float* __restrict__ qb,
    const float* __restrict__ cg, const float* __restrict__ cb)
{
    int warp = (blockIdx.x * blockDim.x + threadIdx.x) >> 5;
    int lane = threadIdx.x & 31;

    const float* src;
    const float* gp;
    const float* bp;
    __nv_bfloat16* dst;
    if (warp < N_SEQ) {
        src = feat + (size_t)warp * D_MODEL;
        gp = qg; bp = qb;
        dst = g_qn_h + (size_t)warp * D_MODEL;
    } else {
        int r = warp - N_SEQ;
        int n = r / LCTX, l = r % LCTX;
        src = (l == 0) ? (feat + (size_t)n * D_MODEL)
                       : (ctx + ((size_t)n * KCTX + (l - 1)) * D_MODEL);
        gp = cg; bp = cb;
        dst = g_cn_h + (size_t)r * D_MODEL;
    }

    float4 x[8];
    float s = 0.f, ss = 0.f;
#pragma unroll
    for (int j = 0; j < 8; j++) {
        x[j] = reinterpret_cast<const float4*>(src)[j * 32 + lane];
        s  += x[j].x + x[j].y + x[j].z + x[j].w;
        ss += x[j].x * x[j].x + x[j].y * x[j].y + x[j].z * x[j].z + x[j].w * x[j].w;
    }
#pragma unroll
    for (int o = 16; o; o >>= 1) {
        s  += __shfl_xor_sync(0xFFFFFFFFu, s,  o);
        ss += __shfl_xor_sync(0xFFFFFFFFu, ss, o);
    }
    float mean = s * (1.f / 1024.f);
    float var  = ss * (1.f / 1024.f) - mean * mean;
    float rstd = rsqrtf(var + 1e-5f);

#pragma unroll
    for (int j = 0; j < 8; j++) {
        float4 g4 = reinterpret_cast<const float4*>(gp)[j * 32 + lane];
        float4 b4 = reinterpret_cast<const float4*>(bp)[j * 32 + lane];
        float yx = (x[j].x - mean) * rstd * g4.x + b4.x;
        float yy = (x[j].y - mean) * rstd * g4.y + b4.y;
        float yz = (x[j].z - mean) * rstd * g4.z + b4.z;
        float yw = (x[j].w - mean) * rstd * g4.w + b4.w;
        __nv_bfloat162 p0 = __floats2bfloat162_rn(yx, yy);
        __nv_bfloat162 p1 = __floats2bfloat162_rn(yz, yw);
        uint2 u;
        u.x = *reinterpret_cast<unsigned int*>(&p0);
        u.y = *reinterpret_cast<unsigned int*>(&p1);
        reinterpret_cast<uint2*>(dst)[j * 32 + lane] = u;
    }
}

// ---------------- bf16 wmma GEMM: C[M,1024] = A[M,1024] @ Wt^T, fp32 out --------
// BM=BN=128, BK=32, 4 warps (2x2), warp tile 64x64, 3-stage cp.async, 2 CTAs/SM.
constexpr int BK = 32;
constexpr int ROWPAD = BK + 8;               // 40 bf16 = 80B row pitch
constexpr int STAGE_BYTES = 256 * ROWPAD * 2;  // A(128) + B(128) rows = 20480 B
constexpr int GEMM_STAGES = 3;
constexpr int GEMM_SMEM_DYN = GEMM_STAGES * STAGE_BYTES;  // 61440
constexpr int NT_K = D_MODEL / BK;           // 32

template<int MODE>  // 0: qn@Wq->q  1: cn@Wk->k  2: cn@Wv->v  3: o@Wout->t
__global__ void __launch_bounds__(128, 2) gemm_kernel()
{
    const __nv_bfloat16* A  = (MODE == 0) ? g_qn_h : (MODE == 3) ? g_o_h : g_cn_h;
    const __nv_bfloat16* Bt = (MODE == 0) ? g_wqt : (MODE == 1) ? g_wkt
                            : (MODE == 2) ? g_wvt : g_wot;
    float* C = (MODE == 0) ? g_q : (MODE == 1) ? g_k : (MODE == 2) ? g_v : g_t;

    extern __shared__ __align__(16) char sm0[];

    int tid = threadIdx.x;
    int wid = tid >> 5;
    size_t bm = (size_t)blockIdx.y * 128;
    int bn = blockIdx.x * 128;

    int wm = (wid >> 1) * 64;   // 2 warps along M
    int wn = (wid & 1) * 64;    // 2 warps along N

    wmma::fragment<wmma::accumulator, 16, 16, 16, float> acc[4][4];
#pragma unroll
    for (int i = 0; i < 4; i++)
#pragma unroll
        for (int j = 0; j < 4; j++) wmma::fill_fragment(acc[i][j], 0.f);

    auto load_stage = [&](int kt) {
        char* base = sm0 + (kt % GEMM_STAGES) * STAGE_BYTES;
        // A: 128 rows x 64B (4 x 16B chunks) = 512 chunks; B same. 4+4 per thread.
#pragma unroll
        for (int i = 0; i < 4; i++) {
            int id = tid + i * 128;
            int row = id >> 2, c = id & 3;
            __pipeline_memcpy_async(base + row * 80 + c * 16,
                                    A + (bm + row) * D_MODEL + kt * BK + c * 8, 16);
        }
#pragma unroll
        for (int i = 0; i < 4; i++) {
            int id = tid + i * 128;
            int row = id >> 2, c = id & 3;
            __pipeline_memcpy_async(base + 128 * 80 + row * 80 + c * 16,
                                    Bt + (size_t)(bn + row) * D_MODEL + kt * BK + c * 8, 16);
        }
    };

    load_stage(0); __pipeline_commit();
    load_stage(1); __pipeline_commit();

    for (int kt = 0; kt < NT_K; kt++) {
        __pipeline_wait_prior(1);
        __syncthreads();

        const __nv_bfloat16* sA = reinterpret_cast<const __nv_bfloat16*>(
            sm0 + (kt % GEMM_STAGES) * STAGE_BYTES);
        const __nv_bfloat16* sB = sA + 128 * ROWPAD;

#pragma unroll
        for (int kk = 0; kk < BK; kk += 16) {
            wmma::fragment<wmma::matrix_a, 16, 16, 16, __nv_bfloat16, wmma::row_major> af[4];
            wmma::fragment<wmma::matrix_b, 16, 16, 16, __nv_bfloat16, wmma::col_major> bf[4];
#pragma unroll
            for (int i = 0; i < 4; i++)
                wmma::load_matrix_sync(af[i], sA + (wm + i * 16) * ROWPAD + kk, ROWPAD);
#pragma unroll
            for (int j = 0; j < 4; j++)
                wmma::load_matrix_sync(bf[j], sB + (wn + j * 16) * ROWPAD + kk, ROWPAD);
#pragma unroll
            for (int i = 0; i < 4; i++)
#pragma unroll
                for (int j = 0; j < 4; j++)
                    wmma::mma_sync(acc[i][j], af[i], bf[j], acc[i][j]);
        }

        if (kt + 2 < NT_K) load_stage(kt + 2);
        __pipeline_commit();
    }

#pragma unroll
    for (int i = 0; i < 4; i++)
#pragma unroll
        for (int j = 0; j < 4; j++)
            wmma::store_matrix_sync(C + (bm + wm + i * 16) * D_MODEL + bn + wn + j * 16,
                                    acc[i][j], D_MODEL, wmma::mem_row_major);
}

// ---------------- attention: one warp per (n, h), L = 9, bf16 output ----------------
__global__ void __launch_bounds__(256) attn_kernel()
{
    int warp = (blockIdx.x * blockDim.x + threadIdx.x) >> 5;
    int lane = threadIdx.x & 31;
    int n = warp >> 4;
    int h = warp & 15;

    size_t qoff = (size_t)n * D_MODEL + h * DHEAD + lane * 2;
    float2 q = *reinterpret_cast<const float2*>(g_q + qoff);

    float sc[LCTX];
#pragma unroll
    for (int l = 0; l < LCTX; l++) {
        size_t koff = (size_t)(n * LCTX + l) * D_MODEL + h * DHEAD + lane * 2;
        float2 kk = *reinterpret_cast<const float2*>(g_k + koff);
        float p = q.x * kk.x + q.y * kk.y;
#pragma unroll
        for (int o = 16; o; o >>= 1) p += __shfl_xor_sync(0xFFFFFFFFu, p, o);
        sc[l] = p * 0.125f;
    }
    float m = sc[0];
#pragma unroll
    for (int l = 1; l < LCTX; l++) m = fmaxf(m, sc[l]);
    float sum = 0.f;
#pragma unroll
    for (int l = 0; l < LCTX; l++) { sc[l] = __expf(sc[l] - m); sum += sc[l]; }
    float inv = 1.f / sum;

    float ox = 0.f, oy = 0.f;
#pragma unroll
    for (int l = 0; l < LCTX; l++) {
        size_t voff = (size_t)(n * LCTX + l) * D_MODEL + h * DHEAD + lane * 2;
        float2 vv = *reinterpret_cast<const float2*>(g_v + voff);
        float p = sc[l] * inv;
        ox = fmaf(p, vv.x, ox);
        oy = fmaf(p, vv.y, oy);
    }
    __nv_bfloat162 o2 = __floats2bfloat162_rn(ox, oy);
    *reinterpret_cast<__nv_bfloat162*>(g_o_h + qoff) = o2;
}

// ---------------- epilogue: out = g_t + bout + feat ----------------
__global__ void __launch_bounds__(256) epilogue_kernel(
    const float* __restrict__ feat, const float* __restrict__ bout,
    float* __restrict__ out)
{
    size_t total4 = (size_t)N_SEQ * D_MODEL / 4;
    for (size_t i = (size_t)blockIdx.x * blockDim.x + threadIdx.x; i < total4;
         i += (size_t)gridDim.x * blockDim.x) {
        float4 t = reinterpret_cast<const float4*>(g_t)[i];
        float4 f = reinterpret_cast<const float4*>(feat)[i];
        int col = (int)((i * 4) & (D_MODEL - 1));
        float4 b = *reinterpret_cast<const float4*>(bout + col);
        float4 r;
        r.x = t.x + f.x + b.x;
        r.y = t.y + f.y + b.y;
        r.z = t.z + f.z + b.z;
        r.w = t.w + f.w + b.w;
        reinterpret_cast<float4*>(out)[i] = r;
    }
}

// ---------------- launch ----------------
extern "C" void kernel_launch(void* const* d_in, const int* in_sizes, int n_in,
                              void* d_out, int out_size)
{
    const float* feat = (const float*)d_in[0];
    const float* ctx  = (const float*)d_in[1];
    const float* qg   = (const float*)d_in[2];
    const float* qb   = (const float*)d_in[3];
    const float* cg   = (const float*)d_in[4];
    const float* cb   = (const float*)d_in[5];
    const float* Wq   = (const float*)d_in[6];
    const float* Wk   = (const float*)d_in[7];
    const float* Wv   = (const float*)d_in[8];
    const float* Wout = (const float*)d_in[9];
    const float* bout = (const float*)d_in[10];
    float* out = (float*)d_out;

    cudaFuncSetAttribute(gemm_kernel<0>, cudaFuncAttributeMaxDynamicSharedMemorySize, GEMM_SMEM_DYN);
    cudaFuncSetAttribute(gemm_kernel<1>, cudaFuncAttributeMaxDynamicSharedMemorySize, GEMM_SMEM_DYN);
    cudaFuncSetAttribute(gemm_kernel<2>, cudaFuncAttributeMaxDynamicSharedMemorySize, GEMM_SMEM_DYN);
    cudaFuncSetAttribute(gemm_kernel<3>, cudaFuncAttributeMaxDynamicSharedMemorySize, GEMM_SMEM_DYN);

    cvtT_kernel<0><<<dim3(32, 32), 256>>>(Wq);
    cvtT_kernel<1><<<dim3(32, 32), 256>>>(Wk);
    cvtT_kernel<2><<<dim3(32, 32), 256>>>(Wv);
    cvtT_kernel<3><<<dim3(32, 32), 256>>>(Wout);

    ln_kernel<<<(N_SEQ + MROWS_C) / 8, 256>>>(feat, ctx, qg, qb, cg, cb);

    gemm_kernel<0><<<dim3(8, N_SEQ   / 128), 128, GEMM_SMEM_DYN>>>();
    gemm_kernel<1><<<dim3(8, MROWS_C / 128), 128, GEMM_SMEM_DYN>>>();
    gemm_kernel<2><<<dim3(8, MROWS_C / 128), 128, GEMM_SMEM_DYN>>>();

    attn_kernel<<<(N_SEQ * HEADS) / 8, 256>>>();

    gemm_kernel<3><<<dim3(8, N_SEQ / 128), 128, GEMM_SMEM_DYN>>>();

    epilogue_kernel<<<8192, 256>>>(feat, bout, out);
}

// round 6
// speedup vs baseline: 3.7796x; 1.0714x over previous
#include <cuda_runtime.h>
#include <cuda_bf16.h>
#include <cuda_pipeline.h>
#include <mma.h>
#include <cstdint>

using namespace nvcuda;

#define N_SEQ   32768
#define D_MODEL 1024
#define KCTX    8
#define LCTX    9
#define HEADS   16
#define DHEAD   64
#define MROWS_C (N_SEQ * LCTX)   /* 294912 */

// ---------------- scratch (static device globals; no allocation) ----------------
__device__ __nv_bfloat16 g_qn_h[(size_t)N_SEQ   * D_MODEL];
__device__ __nv_bfloat16 g_cn_h[(size_t)MROWS_C * D_MODEL];
__device__ __nv_bfloat16 g_o_h [(size_t)N_SEQ   * D_MODEL];
__device__ float         g_q   [(size_t)N_SEQ   * D_MODEL];   // fp32 q
__device__ __nv_bfloat16 g_k_h [(size_t)MROWS_C * D_MODEL];   // bf16 k
__device__ __nv_bfloat16 g_v_h [(size_t)MROWS_C * D_MODEL];   // bf16 v
// transposed bf16 weights: Wt[n][k] = W[k][n]  (K-major, same layout as A)
__device__ __nv_bfloat16 g_wqt[(size_t)D_MODEL * D_MODEL];
__device__ __nv_bfloat16 g_wkt[(size_t)D_MODEL * D_MODEL];
__device__ __nv_bfloat16 g_wvt[(size_t)D_MODEL * D_MODEL];
__device__ __nv_bfloat16 g_wot[(size_t)D_MODEL * D_MODEL];

// ---------------- weight convert + transpose: Wt[n][k] = bf16(W[k][n]) ---------
template<int W>
__global__ void __launch_bounds__(256) cvtT_kernel(const float* __restrict__ src)
{
    __nv_bfloat16* dst = (W == 0) ? g_wqt : (W == 1) ? g_wkt : (W == 2) ? g_wvt : g_wot;
    __shared__ float t[32][33];
    int tx = threadIdx.x & 31, ty = threadIdx.x >> 5;  // 32 x 8
    int n0 = blockIdx.x * 32, k0 = blockIdx.y * 32;
#pragma unroll
    for (int j = 0; j < 4; j++)
        t[ty + j * 8][tx] = src[(size_t)(k0 + ty + j * 8) * D_MODEL + n0 + tx];
    __syncthreads();
#pragma unroll
    for (int j = 0; j < 4; j++) {
        int n = ty + j * 8;
        dst[(size_t)(n0 + n) * D_MODEL + k0 + tx] = __float2bfloat16(t[tx][n]);
    }
}

// ---------------- LayerNorm: one warp per row of 1024, bf16 output ----------------
__global__ void __launch_bounds__(256) ln_kernel(
    const float* __restrict__ feat, const float* __restrict__ ctx,
    const float* __restrict__ qg, const float* __restrict__ qb,
    const float* __restrict__ cg, const float* __restrict__ cb)
{
    int warp = (blockIdx.x * blockDim.x + threadIdx.x) >> 5;
    int lane = threadIdx.x & 31;

    const float* src;
    const float* gp;
    const float* bp;
    __nv_bfloat16* dst;
    if (warp < N_SEQ) {
        src = feat + (size_t)warp * D_MODEL;
        gp = qg; bp = qb;
        dst = g_qn_h + (size_t)warp * D_MODEL;
    } else {
        int r = warp - N_SEQ;
        int n = r / LCTX, l = r % LCTX;
        src = (l == 0) ? (feat + (size_t)n * D_MODEL)
                       : (ctx + ((size_t)n * KCTX + (l - 1)) * D_MODEL);
        gp = cg; bp = cb;
        dst = g_cn_h + (size_t)r * D_MODEL;
    }

    float4 x[8];
    float s = 0.f, ss = 0.f;
#pragma unroll
    for (int j = 0; j < 8; j++) {
        x[j] = reinterpret_cast<const float4*>(src)[j * 32 + lane];
        s  += x[j].x + x[j].y + x[j].z + x[j].w;
        ss += x[j].x * x[j].x + x[j].y * x[j].y + x[j].z * x[j].z + x[j].w * x[j].w;
    }
#pragma unroll
    for (int o = 16; o; o >>= 1) {
        s  += __shfl_xor_sync(0xFFFFFFFFu, s,  o);
        ss += __shfl_xor_sync(0xFFFFFFFFu, ss, o);
    }
    float mean = s * (1.f / 1024.f);
    float var  = ss * (1.f / 1024.f) - mean * mean;
    float rstd = rsqrtf(var + 1e-5f);

#pragma unroll
    for (int j = 0; j < 8; j++) {
        float4 g4 = reinterpret_cast<const float4*>(gp)[j * 32 + lane];
        float4 b4 = reinterpret_cast<const float4*>(bp)[j * 32 + lane];
        float yx = (x[j].x - mean) * rstd * g4.x + b4.x;
        float yy = (x[j].y - mean) * rstd * g4.y + b4.y;
        float yz = (x[j].z - mean) * rstd * g4.z + b4.z;
        float yw = (x[j].w - mean) * rstd * g4.w + b4.w;
        __nv_bfloat162 p0 = __floats2bfloat162_rn(yx, yy);
        __nv_bfloat162 p1 = __floats2bfloat162_rn(yz, yw);
        uint2 u;
        u.x = *reinterpret_cast<unsigned int*>(&p0);
        u.y = *reinterpret_cast<unsigned int*>(&p1);
        reinterpret_cast<uint2*>(dst)[j * 32 + lane] = u;
    }
}

// ---------------- bf16 wmma GEMM: C[M,1024] = A[M,1024] @ Wt^T ------------------
// BM=BN=128, BK=32, 4 warps (2x2), warp tile 64x64, 4-stage cp.async (depth 3),
// 2 CTAs/SM. MODE 1/2 emit bf16 via smem staging; MODE 3 fuses +bout+feat -> out.
constexpr int BK = 32;
constexpr int ROWPAD = BK + 8;                 // 40 bf16 = 80B row pitch
constexpr int STAGE_BYTES = 256 * ROWPAD * 2;  // A(128)+B(128) rows = 20480 B
constexpr int GEMM_STAGES = 4;
constexpr int GEMM_SMEM_DYN = GEMM_STAGES * STAGE_BYTES;  // 81920
constexpr int NT_K = D_MODEL / BK;             // 32

template<int MODE>  // 0: qn@Wq->q(f32)  1: cn@Wk->k(bf16)  2: cn@Wv->v(bf16)  3: o@Wout->out(fused)
__global__ void __launch_bounds__(128, 2) gemm_kernel(
    const float* __restrict__ feat, const float* __restrict__ bout,
    float* __restrict__ outp)
{
    const __nv_bfloat16* A  = (MODE == 0) ? g_qn_h : (MODE == 3) ? g_o_h : g_cn_h;
    const __nv_bfloat16* Bt = (MODE == 0) ? g_wqt : (MODE == 1) ? g_wkt
                            : (MODE == 2) ? g_wvt : g_wot;

    extern __shared__ __align__(16) char sm0[];

    int tid = threadIdx.x;
    int wid = tid >> 5, lane = tid & 31;
    size_t bm = (size_t)blockIdx.y * 128;
    int bn = blockIdx.x * 128;

    int wm = (wid >> 1) * 64;   // 2 warps along M
    int wn = (wid & 1) * 64;    // 2 warps along N

    wmma::fragment<wmma::accumulator, 16, 16, 16, float> acc[4][4];
#pragma unroll
    for (int i = 0; i < 4; i++)
#pragma unroll
        for (int j = 0; j < 4; j++) wmma::fill_fragment(acc[i][j], 0.f);

    auto load_stage = [&](int kt) {
        char* base = sm0 + (kt % GEMM_STAGES) * STAGE_BYTES;
#pragma unroll
        for (int i = 0; i < 4; i++) {
            int id = tid + i * 128;
            int row = id >> 2, c = id & 3;
            __pipeline_memcpy_async(base + row * 80 + c * 16,
                                    A + (bm + row) * D_MODEL + kt * BK + c * 8, 16);
        }
#pragma unroll
        for (int i = 0; i < 4; i++) {
            int id = tid + i * 128;
            int row = id >> 2, c = id & 3;
            __pipeline_memcpy_async(base + 128 * 80 + row * 80 + c * 16,
                                    Bt + (size_t)(bn + row) * D_MODEL + kt * BK + c * 8, 16);
        }
    };

    load_stage(0); __pipeline_commit();
    load_stage(1); __pipeline_commit();
    load_stage(2); __pipeline_commit();

    for (int kt = 0; kt < NT_K; kt++) {
        __pipeline_wait_prior(2);
        __syncthreads();

        const __nv_bfloat16* sA = reinterpret_cast<const __nv_bfloat16*>(
            sm0 + (kt % GEMM_STAGES) * STAGE_BYTES);
        const __nv_bfloat16* sB = sA + 128 * ROWPAD;

#pragma unroll
        for (int kk = 0; kk < BK; kk += 16) {
            wmma::fragment<wmma::matrix_a, 16, 16, 16, __nv_bfloat16, wmma::row_major> af[4];
            wmma::fragment<wmma::matrix_b, 16, 16, 16, __nv_bfloat16, wmma::col_major> bf[4];
#pragma unroll
            for (int i = 0; i < 4; i++)
                wmma::load_matrix_sync(af[i], sA + (wm + i * 16) * ROWPAD + kk, ROWPAD);
#pragma unroll
            for (int j = 0; j < 4; j++)
                wmma::load_matrix_sync(bf[j], sB + (wn + j * 16) * ROWPAD + kk, ROWPAD);
#pragma unroll
            for (int i = 0; i < 4; i++)
#pragma unroll
                for (int j = 0; j < 4; j++)
                    wmma::mma_sync(acc[i][j], af[i], bf[j], acc[i][j]);
        }

        if (kt + 3 < NT_K) load_stage(kt + 3);
        __pipeline_commit();
    }

    if (MODE == 0) {
        // direct fp32 store
#pragma unroll
        for (int i = 0; i < 4; i++)
#pragma unroll
            for (int j = 0; j < 4; j++)
                wmma::store_matrix_sync(g_q + (bm + wm + i * 16) * D_MODEL + bn + wn + j * 16,
                                        acc[i][j], D_MODEL, wmma::mem_row_major);
        return;
    }

    // smem-staged epilogue (per-warp 16x64 f32 region = 4KB)
    __syncthreads();
    float* stage = reinterpret_cast<float*>(sm0) + wid * 1024;

    if (MODE == 1 || MODE == 2) {
        __nv_bfloat16* Ch = (MODE == 1) ? g_k_h : g_v_h;
#pragma unroll
        for (int i = 0; i < 4; i++) {
#pragma unroll
            for (int j = 0; j < 4; j++)
                wmma::store_matrix_sync(stage + j * 16, acc[i][j], 64, wmma::mem_row_major);
            __syncwarp();
            size_t grow = bm + wm + i * 16;
#pragma unroll
            for (int u = 0; u < 16; u++) {
                int e = lane + u * 32;           // 0..511 (16 rows x 32 bf162 cols)
                int r = e >> 5, c2 = e & 31;
                float2 f2 = *reinterpret_cast<const float2*>(stage + r * 64 + c2 * 2);
                __nv_bfloat162 h2 = __floats2bfloat162_rn(f2.x, f2.y);
                *reinterpret_cast<__nv_bfloat162*>(
                    Ch + (grow + r) * D_MODEL + bn + wn + c2 * 2) = h2;
            }
            __syncwarp();
        }
    } else {
        // MODE 3: out = acc + bout + feat
#pragma unroll
        for (int i = 0; i < 4; i++) {
#pragma unroll
            for (int j = 0; j < 4; j++)
                wmma::store_matrix_sync(stage + j * 16, acc[i][j], 64, wmma::mem_row_major);
            __syncwarp();
            size_t grow = bm + wm + i * 16;
#pragma unroll
            for (int u = 0; u < 16; u++) {
                int e = lane + u * 32;
                int r = e >> 5, c2 = e & 31;
                int gc = bn + wn + c2 * 2;
                float2 f2 = *reinterpret_cast<const float2*>(stage + r * 64 + c2 * 2);
                float2 b2 = *reinterpret_cast<const float2*>(bout + gc);
                float2 ff = *reinterpret_cast<const float2*>(feat + (grow + r) * D_MODEL + gc);
                float2 o2;
                o2.x = f2.x + b2.x + ff.x;
                o2.y = f2.y + b2.y + ff.y;
                *reinterpret_cast<float2*>(outp + (grow + r) * D_MODEL + gc) = o2;
            }
            __syncwarp();
        }
    }
}

// ---------------- attention: one warp per (n, h), L = 9, bf16 k/v ----------------
__global__ void __launch_bounds__(256) attn_kernel()
{
    int warp = (blockIdx.x * blockDim.x + threadIdx.x) >> 5;
    int lane = threadIdx.x & 31;
    int n = warp >> 4;
    int h = warp & 15;

    size_t qoff = (size_t)n * D_MODEL + h * DHEAD + lane * 2;
    float2 q = *reinterpret_cast<const float2*>(g_q + qoff);

    float sc[LCTX];
#pragma unroll
    for (int l = 0; l < LCTX; l++) {
        size_t koff = (size_t)(n * LCTX + l) * D_MODEL + h * DHEAD + lane * 2;
        __nv_bfloat162 k2 = *reinterpret_cast<const __nv_bfloat162*>(g_k_h + koff);
        float2 kk = __bfloat1622float2(k2);
        float p = q.x * kk.x + q.y * kk.y;
#pragma unroll
        for (int o = 16; o; o >>= 1) p += __shfl_xor_sync(0xFFFFFFFFu, p, o);
        sc[l] = p * 0.125f;
    }
    float m = sc[0];
#pragma unroll
    for (int l = 1; l < LCTX; l++) m = fmaxf(m, sc[l]);
    float sum = 0.f;
#pragma unroll
    for (int l = 0; l < LCTX; l++) { sc[l] = __expf(sc[l] - m); sum += sc[l]; }
    float inv = 1.f / sum;

    float ox = 0.f, oy = 0.f;
#pragma unroll
    for (int l = 0; l < LCTX; l++) {
        size_t voff = (size_t)(n * LCTX + l) * D_MODEL + h * DHEAD + lane * 2;
        __nv_bfloat162 v2 = *reinterpret_cast<const __nv_bfloat162*>(g_v_h + voff);
        float2 vv = __bfloat1622float2(v2);
        float p = sc[l] * inv;
        ox = fmaf(p, vv.x, ox);
        oy = fmaf(p, vv.y, oy);
    }
    __nv_bfloat162 o2 = __floats2bfloat162_rn(ox, oy);
    *reinterpret_cast<__nv_bfloat162*>(g_o_h + qoff) = o2;
}

// ---------------- launch ----------------
extern "C" void kernel_launch(void* const* d_in, const int* in_sizes, int n_in,
                              void* d_out, int out_size)
{
    const float* feat = (const float*)d_in[0];
    const float* ctx  = (const float*)d_in[1];
    const float* qg   = (const float*)d_in[2];
    const float* qb   = (const float*)d_in[3];
    const float* cg   = (const float*)d_in[4];
    const float* cb   = (const float*)d_in[5];
    const float* Wq   = (const float*)d_in[6];
    const float* Wk   = (const float*)d_in[7];
    const float* Wv   = (const float*)d_in[8];
    const float* Wout = (const float*)d_in[9];
    const float* bout = (const float*)d_in[10];
    float* out = (float*)d_out;

    cudaFuncSetAttribute(gemm_kernel<0>, cudaFuncAttributeMaxDynamicSharedMemorySize, GEMM_SMEM_DYN);
    cudaFuncSetAttribute(gemm_kernel<1>, cudaFuncAttributeMaxDynamicSharedMemorySize, GEMM_SMEM_DYN);
    cudaFuncSetAttribute(gemm_kernel<2>, cudaFuncAttributeMaxDynamicSharedMemorySize, GEMM_SMEM_DYN);
    cudaFuncSetAttribute(gemm_kernel<3>, cudaFuncAttributeMaxDynamicSharedMemorySize, GEMM_SMEM_DYN);

    cvtT_kernel<0><<<dim3(32, 32), 256>>>(Wq);
    cvtT_kernel<1><<<dim3(32, 32), 256>>>(Wk);
    cvtT_kernel<2><<<dim3(32, 32), 256>>>(Wv);
    cvtT_kernel<3><<<dim3(32, 32), 256>>>(Wout);

    ln_kernel<<<(N_SEQ + MROWS_C) / 8, 256>>>(feat, ctx, qg, qb, cg, cb);

    gemm_kernel<0><<<dim3(8, N_SEQ   / 128), 128, GEMM_SMEM_DYN>>>(nullptr, nullptr, nullptr);
    gemm_kernel<1><<<dim3(8, MROWS_C / 128), 128, GEMM_SMEM_DYN>>>(nullptr, nullptr, nullptr);
    gemm_kernel<2><<<dim3(8, MROWS_C / 128), 128, GEMM_SMEM_DYN>>>(nullptr, nullptr, nullptr);

    attn_kernel<<<(N_SEQ * HEADS) / 8, 256>>>();

    gemm_kernel<3><<<dim3(8, N_SEQ / 128), 128, GEMM_SMEM_DYN>>>(feat, bout, out);
}